// round 1
// baseline (speedup 1.0000x reference)
#include <cuda_runtime.h>
#include <cuda_bf16.h>
#include <cstddef>

// Problem constants
#define B_   2
#define LQ_  2048
#define LKV_ 2048
#define DQ_  1024
#define HID_ 1024
#define NH_  16
#define HD_  64
#define EPS_ 1e-5f

// Scratch (allocation-free rule: __device__ globals)
__device__ float g_Qp[B_ * LQ_ * HID_];
__device__ float g_Kp[B_ * LKV_ * HID_];
__device__ float g_Vp[B_ * LKV_ * HID_];
__device__ float g_Ctx[B_ * LQ_ * HID_];
__device__ float g_X[B_ * LQ_ * DQ_];

// ---------------------------------------------------------------------------
// GEMM: C[M,N] = A[M,K] @ W[K,N] + bias[N] (+ residual[M,N] if non-null)
// 64x64 block tile, BK=16, 16x16 threads, 4x4 microtile.
// ---------------------------------------------------------------------------
#define BM 64
#define BN 64
#define BK 16

__global__ __launch_bounds__(256) void gemm_bias_kernel(
    const float* __restrict__ A, const float* __restrict__ W,
    const float* __restrict__ bias, const float* __restrict__ residual,
    float* __restrict__ C, int M, int N, int K)
{
    __shared__ float As[BM][BK];
    __shared__ float Bs[BK][BN + 4];   // pad to dodge store conflicts

    const int tx = threadIdx.x;        // 0..15
    const int ty = threadIdx.y;        // 0..15
    const int tid = ty * 16 + tx;
    const int row0 = blockIdx.y * BM;
    const int col0 = blockIdx.x * BN;

    float acc[4][4] = {};

    for (int k0 = 0; k0 < K; k0 += BK) {
        // A tile 64x16: thread -> one float4
        {
            int r = tid >> 2;
            int c = (tid & 3) << 2;
            float4 v = *(const float4*)&A[(size_t)(row0 + r) * K + k0 + c];
            As[r][c]     = v.x;
            As[r][c + 1] = v.y;
            As[r][c + 2] = v.z;
            As[r][c + 3] = v.w;
        }
        // B tile 16x64: thread -> one float4
        {
            int r = tid >> 4;
            int c = (tid & 15) << 2;
            float4 v = *(const float4*)&W[(size_t)(k0 + r) * N + col0 + c];
            Bs[r][c]     = v.x;
            Bs[r][c + 1] = v.y;
            Bs[r][c + 2] = v.z;
            Bs[r][c + 3] = v.w;
        }
        __syncthreads();

        #pragma unroll
        for (int kk = 0; kk < BK; kk++) {
            float a[4], b[4];
            #pragma unroll
            for (int i = 0; i < 4; i++) a[i] = As[ty * 4 + i][kk];
            #pragma unroll
            for (int j = 0; j < 4; j++) b[j] = Bs[kk][tx * 4 + j];
            #pragma unroll
            for (int i = 0; i < 4; i++)
                #pragma unroll
                for (int j = 0; j < 4; j++)
                    acc[i][j] += a[i] * b[j];
        }
        __syncthreads();
    }

    #pragma unroll
    for (int i = 0; i < 4; i++) {
        int r = row0 + ty * 4 + i;
        #pragma unroll
        for (int j = 0; j < 4; j++) {
            int c = col0 + tx * 4 + j;
            float v = acc[i][j] + bias[c];
            if (residual) v += residual[(size_t)r * N + c];
            C[(size_t)r * N + c] = v;
        }
    }
}

// ---------------------------------------------------------------------------
// Flash-attention (fp32). Block = 64 queries of one (b, h). 64 threads; each
// thread owns one query row: q[64], o[64] in registers. K/V 64x64 tiles in
// smem; S in smem with [j][tid] layout (conflict-free column per thread).
// ---------------------------------------------------------------------------
__global__ __launch_bounds__(64) void attention_kernel(
    const float* __restrict__ Qp, const float* __restrict__ Kp,
    const float* __restrict__ Vp, float* __restrict__ Ctx)
{
    __shared__ float Ks[64][64];
    __shared__ float Vs[64][64];
    __shared__ float Ss[64][64];

    const int tid = threadIdx.x;           // query row within tile
    const int b = blockIdx.z;
    const int h = blockIdx.y;
    const int q0 = blockIdx.x * 64;
    const float scale = 0.125f;            // 1/sqrt(64)

    float q[64], o[64];
    {
        const float* qptr = Qp + ((size_t)(b * LQ_ + q0 + tid) * HID_ + h * HD_);
        #pragma unroll
        for (int d4 = 0; d4 < 16; d4++) {
            float4 v = *(const float4*)&qptr[d4 * 4];
            q[d4 * 4]     = v.x * scale;
            q[d4 * 4 + 1] = v.y * scale;
            q[d4 * 4 + 2] = v.z * scale;
            q[d4 * 4 + 3] = v.w * scale;
        }
        #pragma unroll
        for (int d = 0; d < 64; d++) o[d] = 0.f;
    }

    float m = -1e30f, l = 0.f;

    for (int kt = 0; kt < LKV_; kt += 64) {
        // Load K,V tiles (coalesced: thread tid loads column tid)
        const float* kbase = Kp + ((size_t)(b * LKV_ + kt) * HID_ + h * HD_);
        const float* vbase = Vp + ((size_t)(b * LKV_ + kt) * HID_ + h * HD_);
        #pragma unroll 8
        for (int i = 0; i < 64; i++) {
            Ks[i][tid] = kbase[(size_t)i * HID_ + tid];
            Vs[i][tid] = vbase[(size_t)i * HID_ + tid];
        }
        __syncthreads();

        // S = q . K_j  (K row broadcast across threads, float4 vectorized)
        float mloc = -1e30f;
        #pragma unroll 2
        for (int j = 0; j < 64; j++) {
            const float4* k4 = (const float4*)Ks[j];
            float s = 0.f;
            #pragma unroll
            for (int d4 = 0; d4 < 16; d4++) {
                float4 kv = k4[d4];
                s += q[d4 * 4]     * kv.x;
                s += q[d4 * 4 + 1] * kv.y;
                s += q[d4 * 4 + 2] * kv.z;
                s += q[d4 * 4 + 3] * kv.w;
            }
            Ss[j][tid] = s;
            mloc = fmaxf(mloc, s);
        }

        // online softmax rescale
        float mnew = fmaxf(m, mloc);
        float corr = __expf(m - mnew);
        l *= corr;
        #pragma unroll
        for (int d = 0; d < 64; d++) o[d] *= corr;

        float lad = 0.f;
        #pragma unroll 4
        for (int j = 0; j < 64; j++) {
            float p = __expf(Ss[j][tid] - mnew);
            lad += p;
            Ss[j][tid] = p;
        }
        l += lad;
        m = mnew;

        // O += P @ V  (V row broadcast, float4 vectorized)
        #pragma unroll 2
        for (int j = 0; j < 64; j++) {
            float p = Ss[j][tid];
            const float4* v4 = (const float4*)Vs[j];
            #pragma unroll
            for (int d4 = 0; d4 < 16; d4++) {
                float4 vv = v4[d4];
                o[d4 * 4]     += p * vv.x;
                o[d4 * 4 + 1] += p * vv.y;
                o[d4 * 4 + 2] += p * vv.z;
                o[d4 * 4 + 3] += p * vv.w;
            }
        }
        __syncthreads();
    }

    const float inv = 1.f / l;
    float* optr = Ctx + ((size_t)(b * LQ_ + q0 + tid) * HID_ + h * HD_);
    #pragma unroll
    for (int d4 = 0; d4 < 16; d4++) {
        float4 v;
        v.x = o[d4 * 4]     * inv;
        v.y = o[d4 * 4 + 1] * inv;
        v.z = o[d4 * 4 + 2] * inv;
        v.w = o[d4 * 4 + 3] * inv;
        *(float4*)&optr[d4 * 4] = v;
    }
}

// ---------------------------------------------------------------------------
// LayerNorm over rows of 1024. One block (256 threads) per row.
// ---------------------------------------------------------------------------
__global__ __launch_bounds__(256) void layernorm_kernel(
    const float* __restrict__ X, const float* __restrict__ gamma,
    const float* __restrict__ beta, float* __restrict__ out)
{
    __shared__ float red_s[8];
    __shared__ float red_ss[8];

    const int row = blockIdx.x;
    const int tid = threadIdx.x;
    const float* x = X + (size_t)row * DQ_;

    float s = 0.f, ss = 0.f;
    #pragma unroll
    for (int i = tid; i < DQ_; i += 256) {
        float v = x[i];
        s += v;
        ss += v * v;
    }
    // warp reduce
    #pragma unroll
    for (int off = 16; off > 0; off >>= 1) {
        s  += __shfl_xor_sync(0xffffffff, s, off);
        ss += __shfl_xor_sync(0xffffffff, ss, off);
    }
    if ((tid & 31) == 0) {
        red_s[tid >> 5] = s;
        red_ss[tid >> 5] = ss;
    }
    __syncthreads();
    if (tid < 32) {
        float a = (tid < 8) ? red_s[tid] : 0.f;
        float b = (tid < 8) ? red_ss[tid] : 0.f;
        #pragma unroll
        for (int off = 4; off > 0; off >>= 1) {
            a += __shfl_xor_sync(0xffffffff, a, off);
            b += __shfl_xor_sync(0xffffffff, b, off);
        }
        if (tid == 0) { red_s[0] = a; red_ss[0] = b; }
    }
    __syncthreads();

    const float mu = red_s[0] * (1.f / DQ_);
    const float var = red_ss[0] * (1.f / DQ_) - mu * mu;
    const float rstd = rsqrtf(var + EPS_);

    float* orow = out + (size_t)row * DQ_;
    for (int i = tid; i < DQ_; i += 256) {
        orow[i] = (x[i] - mu) * rstd * gamma[i] + beta[i];
    }
}

// ---------------------------------------------------------------------------
// Launch
// ---------------------------------------------------------------------------
extern "C" void kernel_launch(void* const* d_in, const int* in_sizes, int n_in,
                              void* d_out, int out_size)
{
    const float* query     = (const float*)d_in[0];
    const float* key_value = (const float*)d_in[1];
    const float* Wq = (const float*)d_in[2];
    const float* bq = (const float*)d_in[3];
    const float* Wk = (const float*)d_in[4];
    const float* bk = (const float*)d_in[5];
    const float* Wv = (const float*)d_in[6];
    const float* bv = (const float*)d_in[7];
    const float* Wo = (const float*)d_in[8];
    const float* bo = (const float*)d_in[9];
    const float* ln_gamma = (const float*)d_in[10];
    const float* ln_beta  = (const float*)d_in[11];
    float* out = (float*)d_out;

    float *Qp, *Kp, *Vp, *Ctx, *X;
    cudaGetSymbolAddress((void**)&Qp, g_Qp);
    cudaGetSymbolAddress((void**)&Kp, g_Kp);
    cudaGetSymbolAddress((void**)&Vp, g_Vp);
    cudaGetSymbolAddress((void**)&Ctx, g_Ctx);
    cudaGetSymbolAddress((void**)&X, g_X);

    const int M = B_ * LQ_;   // 4096
    const int K = DQ_;        // 1024
    const int N = HID_;       // 1024

    dim3 gblock(16, 16);
    dim3 ggrid(N / BN, M / BM);

    // Projections
    gemm_bias_kernel<<<ggrid, gblock>>>(query,     Wq, bq, nullptr, Qp, M, N, K);
    gemm_bias_kernel<<<ggrid, gblock>>>(key_value, Wk, bk, nullptr, Kp, M, N, K);
    gemm_bias_kernel<<<ggrid, gblock>>>(key_value, Wv, bv, nullptr, Vp, M, N, K);

    // Attention
    dim3 agrid(LQ_ / 64, NH_, B_);
    attention_kernel<<<agrid, 64>>>(Qp, Kp, Vp, Ctx);

    // Output projection + residual
    gemm_bias_kernel<<<ggrid, gblock>>>(Ctx, Wo, bo, query, X, M, DQ_, HID_);

    // LayerNorm
    layernorm_kernel<<<M, 256>>>(X, ln_gamma, ln_beta, out);
}

// round 2
// speedup vs baseline: 3.9658x; 3.9658x over previous
#include <cuda_runtime.h>
#include <cstdint>
#include <cstddef>

// Problem constants
#define B_   2
#define LQ_  2048
#define LKV_ 2048
#define DQ_  1024
#define HID_ 1024
#define NH_  16
#define HD_  64
#define EPS_ 1e-5f

// Scratch (allocation-free rule: __device__ globals)
__device__ float g_Qp[B_ * LQ_ * HID_];
__device__ float g_Kp[B_ * LKV_ * HID_];
__device__ float g_Vp[B_ * LKV_ * HID_];
__device__ float g_Ctx[B_ * LQ_ * HID_];
__device__ float g_X[B_ * LQ_ * DQ_];

// ---------------------------------------------------------------------------
// Helpers
// ---------------------------------------------------------------------------
__device__ __forceinline__ uint32_t f2tf32(float x) {
    uint32_t r;
    asm("cvt.rna.tf32.f32 %0, %1;" : "=r"(r) : "f"(x));
    return r;
}

// D = A(16x8,row) * B(8x8,col) + D ; tf32 in, fp32 accum
__device__ __forceinline__ void mma_tf32(float c[4], const uint32_t a[4], const uint32_t b[2]) {
    asm volatile(
        "mma.sync.aligned.m16n8k8.row.col.f32.tf32.tf32.f32 "
        "{%0,%1,%2,%3}, {%4,%5,%6,%7}, {%8,%9}, {%0,%1,%2,%3};\n"
        : "+f"(c[0]), "+f"(c[1]), "+f"(c[2]), "+f"(c[3])
        : "r"(a[0]), "r"(a[1]), "r"(a[2]), "r"(a[3]), "r"(b[0]), "r"(b[1]));
}

// FMA-only 2^x (no MUFU). |err| ~ 2e-6 rel. Valid for x <= ~120.
__device__ __forceinline__ float exp2_fast(float x) {
    x = fmaxf(x, -120.f);
    float t = x + 12582912.f;                       // 1.5 * 2^23 magic
    int n = __float_as_int(t) - 0x4B400000;         // round-to-nearest int(x)
    float f = x - (t - 12582912.f);                 // frac in [-0.5, 0.5]
    float p = 1.33335581e-3f;
    p = fmaf(p, f, 9.61812910e-3f);
    p = fmaf(p, f, 5.55041087e-2f);
    p = fmaf(p, f, 2.40226507e-1f);
    p = fmaf(p, f, 6.93147182e-1f);
    p = fmaf(p, f, 1.0f);
    return __int_as_float(__float_as_int(p) + (n << 23));
}

// ---------------------------------------------------------------------------
// TF32 GEMM: C[M,N] = A[M,K] @ W[K,N] + bias (+ residual)
// Block tile 128x128, BK=32, 256 threads (8 warps, 2x4), warp tile 64x32.
// ---------------------------------------------------------------------------
#define GBM 128
#define GBN 128
#define GBK 32
#define AS_LD 36
#define BS_LD 132

__global__ __launch_bounds__(256) void gemm_tf32_kernel(
    const float* __restrict__ A, const float* __restrict__ W,
    const float* __restrict__ bias, const float* __restrict__ residual,
    float* __restrict__ C, int M, int N, int K)
{
    __shared__ uint32_t As[GBM * AS_LD];
    __shared__ uint32_t Bs[GBK * BS_LD];

    const int tid  = threadIdx.x;
    const int lane = tid & 31;
    const int warp = tid >> 5;
    const int warpRow = (warp >> 2) * 64;
    const int warpCol = (warp & 3) * 32;
    const int row0 = blockIdx.y * GBM;
    const int col0 = blockIdx.x * GBN;

    float cf[4][4][4];
    #pragma unroll
    for (int mt = 0; mt < 4; mt++)
        #pragma unroll
        for (int nt = 0; nt < 4; nt++)
            #pragma unroll
            for (int i = 0; i < 4; i++) cf[mt][nt][i] = 0.f;

    for (int k0 = 0; k0 < K; k0 += GBK) {
        // A tile 128x32
        #pragma unroll
        for (int i = 0; i < 4; i++) {
            int r = (tid >> 3) + 32 * i;
            int c = (tid & 7) * 4;
            float4 v = *(const float4*)&A[(size_t)(row0 + r) * K + k0 + c];
            As[r * AS_LD + c]     = f2tf32(v.x);
            As[r * AS_LD + c + 1] = f2tf32(v.y);
            As[r * AS_LD + c + 2] = f2tf32(v.z);
            As[r * AS_LD + c + 3] = f2tf32(v.w);
        }
        // W tile 32x128
        #pragma unroll
        for (int i = 0; i < 4; i++) {
            int lin = tid + 256 * i;
            int r = lin >> 5;
            int c = (lin & 31) * 4;
            float4 v = *(const float4*)&W[(size_t)(k0 + r) * N + col0 + c];
            Bs[r * BS_LD + c]     = f2tf32(v.x);
            Bs[r * BS_LD + c + 1] = f2tf32(v.y);
            Bs[r * BS_LD + c + 2] = f2tf32(v.z);
            Bs[r * BS_LD + c + 3] = f2tf32(v.w);
        }
        __syncthreads();

        #pragma unroll
        for (int ks = 0; ks < 4; ks++) {
            uint32_t af[4][4], bf[4][2];
            #pragma unroll
            for (int mt = 0; mt < 4; mt++) {
                int r = warpRow + 16 * mt + (lane >> 2);
                int c = 8 * ks + (lane & 3);
                af[mt][0] = As[r * AS_LD + c];
                af[mt][1] = As[(r + 8) * AS_LD + c];
                af[mt][2] = As[r * AS_LD + c + 4];
                af[mt][3] = As[(r + 8) * AS_LD + c + 4];
            }
            #pragma unroll
            for (int nt = 0; nt < 4; nt++) {
                int c = warpCol + 8 * nt + (lane >> 2);
                int r = 8 * ks + (lane & 3);
                bf[nt][0] = Bs[r * BS_LD + c];
                bf[nt][1] = Bs[(r + 4) * BS_LD + c];
            }
            #pragma unroll
            for (int mt = 0; mt < 4; mt++)
                #pragma unroll
                for (int nt = 0; nt < 4; nt++)
                    mma_tf32(cf[mt][nt], af[mt], bf[nt]);
        }
        __syncthreads();
    }

    // Epilogue: bias (+residual), float2 stores
    #pragma unroll
    for (int mt = 0; mt < 4; mt++) {
        int r  = row0 + warpRow + 16 * mt + (lane >> 2);
        int r2 = r + 8;
        #pragma unroll
        for (int nt = 0; nt < 4; nt++) {
            int c = col0 + warpCol + 8 * nt + 2 * (lane & 3);
            float b0 = bias[c], b1 = bias[c + 1];
            float v0 = cf[mt][nt][0] + b0, v1 = cf[mt][nt][1] + b1;
            float v2 = cf[mt][nt][2] + b0, v3 = cf[mt][nt][3] + b1;
            if (residual) {
                v0 += residual[(size_t)r  * N + c];
                v1 += residual[(size_t)r  * N + c + 1];
                v2 += residual[(size_t)r2 * N + c];
                v3 += residual[(size_t)r2 * N + c + 1];
            }
            float2 s0 = make_float2(v0, v1);
            float2 s1 = make_float2(v2, v3);
            *(float2*)&C[(size_t)r  * N + c] = s0;
            *(float2*)&C[(size_t)r2 * N + c] = s1;
        }
    }
}

// ---------------------------------------------------------------------------
// Flash attention on tensor cores (tf32 mma, fp32 softmax, FMA-only exp2).
// Block: 128 threads (4 warps), 64 queries of one (b,h); warp owns 16 rows.
// KV tiles of 64. Q pre-scaled by (1/sqrt(HD)) * log2(e) -> exp2 domain.
// Dynamic smem: Qs/Ps 64x68, Ks 64x68, Vs 64x72 (u32 tf32 payloads).
// ---------------------------------------------------------------------------
#define QS_LD 68
#define KS_LD 68
#define VS_LD 72
#define ATT_SMEM ((64 * QS_LD + 64 * KS_LD + 64 * VS_LD) * 4)

__global__ __launch_bounds__(128) void attention_tc_kernel(
    const float* __restrict__ Qp, const float* __restrict__ Kp,
    const float* __restrict__ Vp, float* __restrict__ Ctx)
{
    extern __shared__ uint32_t dsm[];
    uint32_t* Qs = dsm;                      // reused as Ps after Q-frag load
    uint32_t* Ks = dsm + 64 * QS_LD;
    uint32_t* Vs = dsm + 64 * QS_LD + 64 * KS_LD;
    uint32_t* Ps = Qs;

    const int tid  = threadIdx.x;
    const int lane = tid & 31;
    const int warp = tid >> 5;
    const int b  = blockIdx.z;
    const int h  = blockIdx.y;
    const int q0 = blockIdx.x * 64;
    const float SC = 0.125f * 1.44269504089f;   // 1/sqrt(64) * log2(e)

    // Load Q tile -> smem (scaled, tf32)
    #pragma unroll
    for (int i = 0; i < 8; i++) {
        int f = tid + 128 * i;
        int r = f >> 4;
        int c = (f & 15) * 4;
        float4 v = *(const float4*)&Qp[(size_t)(b * LQ_ + q0 + r) * HID_ + h * HD_ + c];
        Qs[r * QS_LD + c]     = f2tf32(v.x * SC);
        Qs[r * QS_LD + c + 1] = f2tf32(v.y * SC);
        Qs[r * QS_LD + c + 2] = f2tf32(v.z * SC);
        Qs[r * QS_LD + c + 3] = f2tf32(v.w * SC);
    }
    __syncthreads();

    // Q fragments into registers (warp's 16 rows)
    uint32_t qf[8][4];
    const int lr0 = 16 * warp + (lane >> 2);    // local row in [0,64)
    #pragma unroll
    for (int ks = 0; ks < 8; ks++) {
        int c = 8 * ks + (lane & 3);
        qf[ks][0] = Qs[lr0 * QS_LD + c];
        qf[ks][1] = Qs[(lr0 + 8) * QS_LD + c];
        qf[ks][2] = Qs[lr0 * QS_LD + c + 4];
        qf[ks][3] = Qs[(lr0 + 8) * QS_LD + c + 4];
    }

    float of[8][4];
    #pragma unroll
    for (int nt = 0; nt < 8; nt++)
        #pragma unroll
        for (int i = 0; i < 4; i++) of[nt][i] = 0.f;
    float m0 = -1e30f, m1 = -1e30f, l0 = 0.f, l1 = 0.f;

    for (int kt = 0; kt < LKV_; kt += 64) {
        // Load K,V tiles (tf32)
        #pragma unroll
        for (int i = 0; i < 8; i++) {
            int f = tid + 128 * i;
            int r = f >> 4;
            int c = (f & 15) * 4;
            size_t gof = (size_t)(b * LKV_ + kt + r) * HID_ + h * HD_ + c;
            float4 kv = *(const float4*)&Kp[gof];
            Ks[r * KS_LD + c]     = f2tf32(kv.x);
            Ks[r * KS_LD + c + 1] = f2tf32(kv.y);
            Ks[r * KS_LD + c + 2] = f2tf32(kv.z);
            Ks[r * KS_LD + c + 3] = f2tf32(kv.w);
            float4 vv = *(const float4*)&Vp[gof];
            Vs[r * VS_LD + c]     = f2tf32(vv.x);
            Vs[r * VS_LD + c + 1] = f2tf32(vv.y);
            Vs[r * VS_LD + c + 2] = f2tf32(vv.z);
            Vs[r * VS_LD + c + 3] = f2tf32(vv.w);
        }
        __syncthreads();

        // S = Q @ K^T  (n = keys, k = head dim)
        float sf[8][4];
        #pragma unroll
        for (int nt = 0; nt < 8; nt++)
            #pragma unroll
            for (int i = 0; i < 4; i++) sf[nt][i] = 0.f;
        #pragma unroll
        for (int ks = 0; ks < 8; ks++) {
            #pragma unroll
            for (int nt = 0; nt < 8; nt++) {
                uint32_t bfr[2];
                int keyrow = 8 * nt + (lane >> 2);
                int dcol = 8 * ks + (lane & 3);
                bfr[0] = Ks[keyrow * KS_LD + dcol];
                bfr[1] = Ks[keyrow * KS_LD + dcol + 4];
                mma_tf32(sf[nt], qf[ks], bfr);
            }
        }

        // Online softmax (exp2 domain), rows r0 = lr0, r1 = lr0+8
        float mloc0 = -1e30f, mloc1 = -1e30f;
        #pragma unroll
        for (int nt = 0; nt < 8; nt++) {
            mloc0 = fmaxf(mloc0, fmaxf(sf[nt][0], sf[nt][1]));
            mloc1 = fmaxf(mloc1, fmaxf(sf[nt][2], sf[nt][3]));
        }
        mloc0 = fmaxf(mloc0, __shfl_xor_sync(0xffffffff, mloc0, 1));
        mloc0 = fmaxf(mloc0, __shfl_xor_sync(0xffffffff, mloc0, 2));
        mloc1 = fmaxf(mloc1, __shfl_xor_sync(0xffffffff, mloc1, 1));
        mloc1 = fmaxf(mloc1, __shfl_xor_sync(0xffffffff, mloc1, 2));

        float mn0 = fmaxf(m0, mloc0), mn1 = fmaxf(m1, mloc1);
        float corr0 = exp2_fast(m0 - mn0), corr1 = exp2_fast(m1 - mn1);
        m0 = mn0; m1 = mn1;

        float rs0 = 0.f, rs1 = 0.f;
        #pragma unroll
        for (int nt = 0; nt < 8; nt++) {
            float p0 = exp2_fast(sf[nt][0] - mn0);
            float p1 = exp2_fast(sf[nt][1] - mn0);
            float p2 = exp2_fast(sf[nt][2] - mn1);
            float p3 = exp2_fast(sf[nt][3] - mn1);
            rs0 += p0 + p1;
            rs1 += p2 + p3;
            int c = 8 * nt + 2 * (lane & 3);
            Ps[lr0 * QS_LD + c]           = f2tf32(p0);
            Ps[lr0 * QS_LD + c + 1]       = f2tf32(p1);
            Ps[(lr0 + 8) * QS_LD + c]     = f2tf32(p2);
            Ps[(lr0 + 8) * QS_LD + c + 1] = f2tf32(p3);
        }
        rs0 += __shfl_xor_sync(0xffffffff, rs0, 1);
        rs0 += __shfl_xor_sync(0xffffffff, rs0, 2);
        rs1 += __shfl_xor_sync(0xffffffff, rs1, 1);
        rs1 += __shfl_xor_sync(0xffffffff, rs1, 2);
        l0 = l0 * corr0 + rs0;
        l1 = l1 * corr1 + rs1;

        #pragma unroll
        for (int nt = 0; nt < 8; nt++) {
            of[nt][0] *= corr0; of[nt][1] *= corr0;
            of[nt][2] *= corr1; of[nt][3] *= corr1;
        }
        __syncwarp();

        // O += P @ V  (k = keys, n = head dim)
        #pragma unroll
        for (int ks = 0; ks < 8; ks++) {
            uint32_t af[4];
            int c = 8 * ks + (lane & 3);
            af[0] = Ps[lr0 * QS_LD + c];
            af[1] = Ps[(lr0 + 8) * QS_LD + c];
            af[2] = Ps[lr0 * QS_LD + c + 4];
            af[3] = Ps[(lr0 + 8) * QS_LD + c + 4];
            #pragma unroll
            for (int nt = 0; nt < 8; nt++) {
                uint32_t bfr[2];
                int kr = 8 * ks + (lane & 3);
                int dc = 8 * nt + (lane >> 2);
                bfr[0] = Vs[kr * VS_LD + dc];
                bfr[1] = Vs[(kr + 4) * VS_LD + dc];
                mma_tf32(of[nt], af, bfr);
            }
        }
        __syncthreads();
    }

    // Normalize + store
    float inv0 = 1.f / l0, inv1 = 1.f / l1;
    int gr0 = q0 + lr0;
    #pragma unroll
    for (int nt = 0; nt < 8; nt++) {
        int c = 8 * nt + 2 * (lane & 3);
        float2 v0 = make_float2(of[nt][0] * inv0, of[nt][1] * inv0);
        float2 v1 = make_float2(of[nt][2] * inv1, of[nt][3] * inv1);
        *(float2*)&Ctx[(size_t)(b * LQ_ + gr0) * HID_ + h * HD_ + c]     = v0;
        *(float2*)&Ctx[(size_t)(b * LQ_ + gr0 + 8) * HID_ + h * HD_ + c] = v1;
    }
}

// ---------------------------------------------------------------------------
// LayerNorm over rows of 1024. One block (256 threads) per row.
// ---------------------------------------------------------------------------
__global__ __launch_bounds__(256) void layernorm_kernel(
    const float* __restrict__ X, const float* __restrict__ gamma,
    const float* __restrict__ beta, float* __restrict__ out)
{
    __shared__ float red_s[8];
    __shared__ float red_ss[8];

    const int row = blockIdx.x;
    const int tid = threadIdx.x;
    const float* x = X + (size_t)row * DQ_;

    float s = 0.f, ss = 0.f;
    #pragma unroll
    for (int i = tid; i < DQ_; i += 256) {
        float v = x[i];
        s += v;
        ss += v * v;
    }
    #pragma unroll
    for (int off = 16; off > 0; off >>= 1) {
        s  += __shfl_xor_sync(0xffffffff, s, off);
        ss += __shfl_xor_sync(0xffffffff, ss, off);
    }
    if ((tid & 31) == 0) {
        red_s[tid >> 5] = s;
        red_ss[tid >> 5] = ss;
    }
    __syncthreads();
    if (tid < 32) {
        float a = (tid < 8) ? red_s[tid] : 0.f;
        float c = (tid < 8) ? red_ss[tid] : 0.f;
        #pragma unroll
        for (int off = 4; off > 0; off >>= 1) {
            a += __shfl_xor_sync(0xffffffff, a, off);
            c += __shfl_xor_sync(0xffffffff, c, off);
        }
        if (tid == 0) { red_s[0] = a; red_ss[0] = c; }
    }
    __syncthreads();

    const float mu = red_s[0] * (1.f / DQ_);
    const float var = red_ss[0] * (1.f / DQ_) - mu * mu;
    const float rstd = rsqrtf(var + EPS_);

    float* orow = out + (size_t)row * DQ_;
    for (int i = tid; i < DQ_; i += 256) {
        orow[i] = (x[i] - mu) * rstd * gamma[i] + beta[i];
    }
}

// ---------------------------------------------------------------------------
// Launch
// ---------------------------------------------------------------------------
extern "C" void kernel_launch(void* const* d_in, const int* in_sizes, int n_in,
                              void* d_out, int out_size)
{
    const float* query     = (const float*)d_in[0];
    const float* key_value = (const float*)d_in[1];
    const float* Wq = (const float*)d_in[2];
    const float* bq = (const float*)d_in[3];
    const float* Wk = (const float*)d_in[4];
    const float* bk = (const float*)d_in[5];
    const float* Wv = (const float*)d_in[6];
    const float* bv = (const float*)d_in[7];
    const float* Wo = (const float*)d_in[8];
    const float* bo = (const float*)d_in[9];
    const float* ln_gamma = (const float*)d_in[10];
    const float* ln_beta  = (const float*)d_in[11];
    float* out = (float*)d_out;

    float *Qp, *Kp, *Vp, *Ctx, *X;
    cudaGetSymbolAddress((void**)&Qp, g_Qp);
    cudaGetSymbolAddress((void**)&Kp, g_Kp);
    cudaGetSymbolAddress((void**)&Vp, g_Vp);
    cudaGetSymbolAddress((void**)&Ctx, g_Ctx);
    cudaGetSymbolAddress((void**)&X, g_X);

    const int M = B_ * LQ_;   // 4096
    const int K = DQ_;        // 1024
    const int N = HID_;       // 1024

    dim3 ggrid(N / GBN, M / GBM);

    gemm_tf32_kernel<<<ggrid, 256>>>(query,     Wq, bq, nullptr, Qp, M, N, K);
    gemm_tf32_kernel<<<ggrid, 256>>>(key_value, Wk, bk, nullptr, Kp, M, N, K);
    gemm_tf32_kernel<<<ggrid, 256>>>(key_value, Wv, bv, nullptr, Vp, M, N, K);

    cudaFuncSetAttribute(attention_tc_kernel,
                         cudaFuncAttributeMaxDynamicSharedMemorySize, ATT_SMEM);
    dim3 agrid(LQ_ / 64, NH_, B_);
    attention_tc_kernel<<<agrid, 128, ATT_SMEM>>>(Qp, Kp, Vp, Ctx);

    gemm_tf32_kernel<<<ggrid, 256>>>(Ctx, Wo, bo, query, X, M, DQ_, HID_);

    layernorm_kernel<<<M, 256>>>(X, ln_gamma, ln_beta, out);
}